// round 8
// baseline (speedup 1.0000x reference)
#include <cuda_runtime.h>
#include <cuda_bf16.h>

// Problem shape constants (fixed by setup_inputs)
#define B_  2
#define HI  64
#define WI  64
#define DI  32
#define CC  16
#define FF  8
#define HO  128
#define WO  128
#define DO_ 64

typedef unsigned long long u64;

// ---- packed f32x2 helpers (sm_100+; ptxas never emits these from C++) ----
__device__ __forceinline__ u64 fma2(u64 a, u64 b, u64 c) {
    u64 d;
    asm("fma.rn.f32x2 %0, %1, %2, %3;" : "=l"(d) : "l"(a), "l"(b), "l"(c));
    return d;
}
__device__ __forceinline__ u64 add2(u64 a, u64 b) {
    u64 d;
    asm("add.rn.f32x2 %0, %1, %2;" : "=l"(d) : "l"(a), "l"(b));
    return d;
}
__device__ __forceinline__ void ldg128(u64& a, u64& b, const float* p) {
    asm("ld.global.nc.v2.b64 {%0, %1}, [%2];" : "=l"(a), "=l"(b) : "l"(p));
}
__device__ __forceinline__ void lds128(u64& a, u64& b, unsigned addr) {
    asm("ld.shared.v2.b64 {%0, %1}, [%2];" : "=l"(a), "=l"(b) : "r"(addr));
}
__device__ __forceinline__ u64 pack2(float x) {
    u64 d;
    asm("mov.b64 %0, {%1, %1};" : "=l"(d) : "f"(x));
    return d;
}
__device__ __forceinline__ float lo32(u64 a) { return __uint_as_float((unsigned)a); }
__device__ __forceinline__ float hi32(u64 a) { return __uint_as_float((unsigned)(a >> 32)); }
__device__ __forceinline__ u64 sel64(bool p, u64 a, u64 b) { return p ? a : b; }

// Block: 256 threads = 8 warps. Warp w: wo = blockIdx.x*4 + w/2, parity = w&1.
// Lane: cg = lane&3 owns channels [cg*4, cg*4+4); d8 = lane>>2 owns depth-slab
// positions s = 4*d8 + j, j=0..3 (douts 2*s+par). Weights per tap are split
// across the 4 cg lanes (only 1/4 replicated), c-reduction via shfl butterfly
// once per warp at the end.
__global__ __launch_bounds__(256, 2)
void sparse_conv3d_transpose_kernel(const float* __restrict__ images,
                                    const int*   __restrict__ base_plane,
                                    const float* __restrict__ kernel,
                                    const float* __restrict__ defv,
                                    float*       __restrict__ out)
{
    __shared__ __align__(16) float sw[27 * FF * CC];   // 13824 B
    for (int i = threadIdx.x; i < 27 * FF * CC; i += 256) sw[i] = kernel[i];
    __syncthreads();

    const int b    = blockIdx.z;
    const int ho   = blockIdx.y;
    const int warp = threadIdx.x >> 5;
    const int lane = threadIdx.x & 31;
    const int wo   = (blockIdx.x << 2) + (warp >> 1);
    const int par  = warp & 1;
    const int cg   = lane & 3;       // channel-quad owned by this lane
    const int d8   = lane >> 2;      // depth-slab group (4 slabs: 4*d8+j)

    const u64 dv2 = pack2(*defv);
    const int bpv = __ldg(base_plane + (b * HO + ho) * WO + wo);

    const unsigned swbase = (unsigned)__cvta_generic_to_shared(sw) + (unsigned)(cg * 16);

    u64 acc[FF][4];   // [f][j] : partial over this lane's 4 channels (c-even, c-odd pairs)
    #pragma unroll
    for (int f = 0; f < FF; f++)
        #pragma unroll
        for (int j = 0; j < 4; j++) acc[f][j] = 0ull;

    #pragma unroll
    for (int kh = 0; kh < 3; kh++) {
        const int hn = ho + 1 - kh;                 // -1 is odd -> caught by &1
        if ((hn & 1) || hn >= 2 * HI) continue;     // warp-uniform
        const int hi = hn >> 1;
        #pragma unroll
        for (int kw = 0; kw < 3; kw++) {
            const int wn = wo + 1 - kw;
            if ((wn & 1) || wn >= 2 * WI) continue; // warp-uniform
            const int wi = wn >> 1;
            const int bpg = __ldg(base_plane + (b * HO + (hi << 1)) * WO + (wi << 1)) >> 1;
            const float* __restrict__ irow =
                images + (size_t)(((b * HI + hi) * WI + wi) * DI) * CC + cg * 4;
            #pragma unroll
            for (int kd = 0; kd < 3; kd++) {
                const int dn0 = bpv + par + 1 - kd;
                if (dn0 & 1) continue;              // warp-uniform parity tap
                const int K = (dn0 >> 1) - bpg;     // di = s + K

                // load this lane's 4 channel-quads for its 4 slabs
                u64 v[8];
                #pragma unroll
                for (int j = 0; j < 4; j++) {
                    const int di = 4 * d8 + j + K;
                    if (di >= 0 && di < DI) {
                        ldg128(v[2 * j], v[2 * j + 1], irow + di * CC);
                    } else {
                        v[2 * j] = dv2; v[2 * j + 1] = dv2;
                    }
                }

                const unsigned wb = swbase +
                    (unsigned)(((kh * 3 + kw) * 3 + kd) * FF * CC * 4);
                #pragma unroll
                for (int f = 0; f < FF; f++) {
                    u64 w0, w1;
                    lds128(w0, w1, wb + f * (CC * 4));   // 16B: this lane's 4 weights
                    #pragma unroll
                    for (int j = 0; j < 4; j++) {
                        acc[f][j] = fma2(v[2 * j],     w0, acc[f][j]);
                        acc[f][j] = fma2(v[2 * j + 1], w1, acc[f][j]);
                    }
                }
            }
        }
    }

    // Reduce across the 4 cg lanes (channels) with a shfl butterfly, then each
    // lane keeps the result for slab s = 4*d8 + cg and stores it.
    float r[FF];
    #pragma unroll
    for (int f = 0; f < FF; f++) {
        u64 a0 = acc[f][0], a1 = acc[f][1], a2 = acc[f][2], a3 = acc[f][3];
        a0 = add2(a0, __shfl_xor_sync(0xffffffffu, a0, 1));
        a1 = add2(a1, __shfl_xor_sync(0xffffffffu, a1, 1));
        a2 = add2(a2, __shfl_xor_sync(0xffffffffu, a2, 1));
        a3 = add2(a3, __shfl_xor_sync(0xffffffffu, a3, 1));
        a0 = add2(a0, __shfl_xor_sync(0xffffffffu, a0, 2));
        a1 = add2(a1, __shfl_xor_sync(0xffffffffu, a1, 2));
        a2 = add2(a2, __shfl_xor_sync(0xffffffffu, a2, 2));
        a3 = add2(a3, __shfl_xor_sync(0xffffffffu, a3, 2));
        const u64 mine = sel64(cg == 0, a0, sel64(cg == 1, a1, sel64(cg == 2, a2, a3)));
        r[f] = lo32(mine) + hi32(mine);
    }

    const int dout = 2 * (4 * d8 + cg) + par;
    float4* op = (float4*)(out + (((size_t)((b * HO + ho) * WO + wo) * DO_ + dout) * FF));
    op[0] = make_float4(r[0], r[1], r[2], r[3]);
    op[1] = make_float4(r[4], r[5], r[6], r[7]);
}

extern "C" void kernel_launch(void* const* d_in, const int* in_sizes, int n_in,
                              void* d_out, int out_size)
{
    const float* images     = (const float*)d_in[0];   // [2,64,64,32,16] f32
    const int*   base_plane = (const int*)  d_in[1];   // [2,128,128,1] i32
    const float* kern       = (const float*)d_in[2];   // [3,3,3,8,16] f32
    const float* defv       = (const float*)d_in[3];   // scalar f32 (zero)
    float*       out        = (float*)d_out;           // [2,128,128,64,8] f32

    dim3 grid(WO / 4, HO, B_);
    sparse_conv3d_transpose_kernel<<<grid, 256>>>(images, base_plane, kern, defv, out);
}

// round 11
// speedup vs baseline: 1.1733x; 1.1733x over previous
#include <cuda_runtime.h>
#include <cuda_bf16.h>

// Problem shape constants (fixed by setup_inputs)
#define B_  2
#define HI  64
#define WI  64
#define DI  32
#define CC  16
#define FF  8
#define HO  128
#define WO  128
#define DO_ 64

typedef unsigned long long u64;

// ---- packed f32x2 helpers (sm_100+; ptxas never emits these from C++) ----
__device__ __forceinline__ u64 fma2(u64 a, u64 b, u64 c) {
    u64 d;
    asm("fma.rn.f32x2 %0, %1, %2, %3;" : "=l"(d) : "l"(a), "l"(b), "l"(c));
    return d;
}
__device__ __forceinline__ u64 add2(u64 a, u64 b) {
    u64 d;
    asm("add.rn.f32x2 %0, %1, %2;" : "=l"(d) : "l"(a), "l"(b));
    return d;
}
__device__ __forceinline__ void ldg128(u64& a, u64& b, const float* p) {
    asm("ld.global.nc.v2.b64 {%0, %1}, [%2];" : "=l"(a), "=l"(b) : "l"(p));
}
__device__ __forceinline__ void lds128(u64& a, u64& b, unsigned addr) {
    asm("ld.shared.v2.b64 {%0, %1}, [%2];" : "=l"(a), "=l"(b) : "r"(addr));
}
__device__ __forceinline__ u64 pack2(float x) {
    u64 d;
    asm("mov.b64 %0, {%1, %1};" : "=l"(d) : "f"(x));
    return d;
}
__device__ __forceinline__ float lo32(u64 a) { return __uint_as_float((unsigned)a); }
__device__ __forceinline__ float hi32(u64 a) { return __uint_as_float((unsigned)(a >> 32)); }

// Block: 256 threads = 8 warps. Warp w: wo = blockIdx.x*4 + w/2, parity = w&1.
// Lane: cg = lane&1 owns channels [cg*8, cg*8+8); d16 = lane>>1 owns depth
// slabs s = 2*d16 + j, j in {0,1} (douts 2*s+par). Weights per tap are split
// 2-way across cg lanes (8x less replication than full broadcast); channel
// reduction is a single shfl_xor(1) butterfly at the end. Output slab for the
// store works out to s = 2*(lane>>1) + (lane&1) = lane, keeping STG coalesced.
__global__ __launch_bounds__(256, 3)
void sparse_conv3d_transpose_kernel(const float* __restrict__ images,
                                    const int*   __restrict__ base_plane,
                                    const float* __restrict__ kernel,
                                    const float* __restrict__ defv,
                                    float*       __restrict__ out)
{
    __shared__ __align__(16) float sw[27 * FF * CC];   // 13824 B
    for (int i = threadIdx.x; i < 27 * FF * CC; i += 256) sw[i] = kernel[i];
    __syncthreads();

    const int b    = blockIdx.z;
    const int ho   = blockIdx.y;
    const int warp = threadIdx.x >> 5;
    const int lane = threadIdx.x & 31;
    const int wo   = (blockIdx.x << 2) + (warp >> 1);
    const int par  = warp & 1;
    const int cg   = lane & 1;       // channel-octet owned by this lane
    const int d16  = lane >> 1;      // depth-slab group (slabs 2*d16 + j)

    const u64 dv2 = pack2(*defv);
    const int bpv = __ldg(base_plane + (b * HO + ho) * WO + wo);

    const unsigned swbase = (unsigned)__cvta_generic_to_shared(sw) + (unsigned)(cg * 32);

    u64 acc[FF][2];   // [f][j] : partials over this lane's 8 channels (4 c-pairs mixed)
    #pragma unroll
    for (int f = 0; f < FF; f++) { acc[f][0] = 0ull; acc[f][1] = 0ull; }

    #pragma unroll
    for (int kh = 0; kh < 3; kh++) {
        const int hn = ho + 1 - kh;                 // -1 is odd -> caught by &1
        if ((hn & 1) || hn >= 2 * HI) continue;     // warp-uniform
        const int hi = hn >> 1;
        #pragma unroll
        for (int kw = 0; kw < 3; kw++) {
            const int wn = wo + 1 - kw;
            if ((wn & 1) || wn >= 2 * WI) continue; // warp-uniform
            const int wi = wn >> 1;
            const int bpg = __ldg(base_plane + (b * HO + (hi << 1)) * WO + (wi << 1)) >> 1;
            const float* __restrict__ irow =
                images + (size_t)(((b * HI + hi) * WI + wi) * DI) * CC + cg * 8;
            #pragma unroll
            for (int kd = 0; kd < 3; kd++) {
                const int dn0 = bpv + par + 1 - kd;
                if (dn0 & 1) continue;              // warp-uniform parity tap
                const int K = (dn0 >> 1) - bpg;     // di = s + K
                const int base = 2 * d16 + K;       // di for j=0

                // load this lane's 8 channels for its 2 slabs (32 B each)
                u64 v[8];
                const float* p = irow + base * CC;
                if ((unsigned)base < DI) {
                    ldg128(v[0], v[1], p);
                    ldg128(v[2], v[3], p + 4);
                } else { v[0] = dv2; v[1] = dv2; v[2] = dv2; v[3] = dv2; }
                if ((unsigned)(base + 1) < DI) {
                    ldg128(v[4], v[5], p + CC);
                    ldg128(v[6], v[7], p + CC + 4);
                } else { v[4] = dv2; v[5] = dv2; v[6] = dv2; v[7] = dv2; }

                const unsigned wb = swbase +
                    (unsigned)(((kh * 3 + kw) * 3 + kd) * FF * CC * 4);
                #pragma unroll
                for (int f = 0; f < FF; f++) {
                    u64 w0, w1, w2, w3;
                    lds128(w0, w1, wb + f * (CC * 4));        // this lane's 8 weights
                    lds128(w2, w3, wb + f * (CC * 4) + 16);
                    acc[f][0] = fma2(v[0], w0, acc[f][0]);
                    acc[f][0] = fma2(v[1], w1, acc[f][0]);
                    acc[f][0] = fma2(v[2], w2, acc[f][0]);
                    acc[f][0] = fma2(v[3], w3, acc[f][0]);
                    acc[f][1] = fma2(v[4], w0, acc[f][1]);
                    acc[f][1] = fma2(v[5], w1, acc[f][1]);
                    acc[f][1] = fma2(v[6], w2, acc[f][1]);
                    acc[f][1] = fma2(v[7], w3, acc[f][1]);
                }
            }
        }
    }

    // Reduce across the cg pair (other 8 channels) with one shfl_xor, keep the
    // j == cg slab so that the output slab index equals `lane`.
    float r[FF];
    #pragma unroll
    for (int f = 0; f < FF; f++) {
        const u64 a0 = add2(acc[f][0], __shfl_xor_sync(0xffffffffu, acc[f][0], 1));
        const u64 a1 = add2(acc[f][1], __shfl_xor_sync(0xffffffffu, acc[f][1], 1));
        const u64 mine = cg ? a1 : a0;
        r[f] = lo32(mine) + hi32(mine);
    }

    const int dout = 2 * lane + par;
    float4* op = (float4*)(out + (((size_t)((b * HO + ho) * WO + wo) * DO_ + dout) * FF));
    op[0] = make_float4(r[0], r[1], r[2], r[3]);
    op[1] = make_float4(r[4], r[5], r[6], r[7]);
}

extern "C" void kernel_launch(void* const* d_in, const int* in_sizes, int n_in,
                              void* d_out, int out_size)
{
    const float* images     = (const float*)d_in[0];   // [2,64,64,32,16] f32
    const int*   base_plane = (const int*)  d_in[1];   // [2,128,128,1] i32
    const float* kern       = (const float*)d_in[2];   // [3,3,3,8,16] f32
    const float* defv       = (const float*)d_in[3];   // scalar f32 (zero)
    float*       out        = (float*)d_out;           // [2,128,128,64,8] f32

    dim3 grid(WO / 4, HO, B_);
    sparse_conv3d_transpose_kernel<<<grid, 256>>>(images, base_plane, kern, defv, out);
}

// round 12
// speedup vs baseline: 1.2741x; 1.0859x over previous
#include <cuda_runtime.h>
#include <cuda_bf16.h>

// Problem shape constants (fixed by setup_inputs)
#define B_  2
#define HI  64
#define WI  64
#define DI  32
#define CC  16
#define FF  8
#define HO  128
#define WO  128
#define DO_ 64

#define TAPB (FF * CC * 4)   // 512 B of weights per (kh,kw,kd) tap

typedef unsigned long long u64;

// ---- packed f32x2 helpers (sm_100+; ptxas never emits these from C++) ----
__device__ __forceinline__ u64 fma2(u64 a, u64 b, u64 c) {
    u64 d;
    asm("fma.rn.f32x2 %0, %1, %2, %3;" : "=l"(d) : "l"(a), "l"(b), "l"(c));
    return d;
}
__device__ __forceinline__ u64 add2(u64 a, u64 b) {
    u64 d;
    asm("add.rn.f32x2 %0, %1, %2;" : "=l"(d) : "l"(a), "l"(b));
    return d;
}
__device__ __forceinline__ void ldg128(u64& a, u64& b, const float* p) {
    asm("ld.global.nc.v2.b64 {%0, %1}, [%2];" : "=l"(a), "=l"(b) : "l"(p));
}
__device__ __forceinline__ void lds128(u64& a, u64& b, unsigned addr) {
    asm("ld.shared.v2.b64 {%0, %1}, [%2];" : "=l"(a), "=l"(b) : "r"(addr));
}
__device__ __forceinline__ u64 pack2(float x) {
    u64 d;
    asm("mov.b64 %0, {%1, %1};" : "=l"(d) : "f"(x));
    return d;
}
__device__ __forceinline__ float lo32(u64 a) { return __uint_as_float((unsigned)a); }
__device__ __forceinline__ float hi32(u64 a) { return __uint_as_float((unsigned)(a >> 32)); }

// Load one depth-row slice for this lane (8 floats = 4 u64), or default.
__device__ __forceinline__ void load_row(u64 r[4], const float* p, bool ok, u64 dv2) {
    if (ok) { ldg128(r[0], r[1], p); ldg128(r[2], r[3], p + 4); }
    else    { r[0] = dv2; r[1] = dv2; r[2] = dv2; r[3] = dv2; }
}

// One input pixel's depth taps (fully static per MODD specialization).
// MODD=true : taps kd=0 (rows r0, r0+1) and kd=2 (rows r0-1, r0) — 3 row loads.
// MODD=false: tap  kd=1 (rows r0, r0+1).
// wbhw = smem weight base for (kh,kw,kd=0) incl. lane's cg offset.
template<bool MODD>
__device__ __forceinline__ void pixel_taps(const float* __restrict__ irow,
                                           unsigned wbhw, int r0, u64 dv2,
                                           u64 (*acc)[2])
{
    u64 ra[4], rb[4];
    load_row(ra, irow + (long)r0 * CC,       (unsigned)r0       < DI, dv2);
    load_row(rb, irow + (long)(r0 + 1) * CC, (unsigned)(r0 + 1) < DI, dv2);
    if (MODD) {
        u64 rm[4];
        load_row(rm, irow + (long)(r0 - 1) * CC, (unsigned)(r0 - 1) < DI, dv2);
        const unsigned wb0 = wbhw;                // kd = 0 weights
        const unsigned wb2 = wbhw + 2 * TAPB;     // kd = 2 weights
        #pragma unroll
        for (int f = 0; f < FF; f++) {
            u64 w[4], x[4];
            lds128(w[0], w[1], wb0 + f * 64);
            lds128(w[2], w[3], wb0 + f * 64 + 16);
            lds128(x[0], x[1], wb2 + f * 64);
            lds128(x[2], x[3], wb2 + f * 64 + 16);
            #pragma unroll
            for (int q = 0; q < 4; q++) {
                acc[f][0] = fma2(ra[q], w[q], acc[f][0]);
                acc[f][0] = fma2(rm[q], x[q], acc[f][0]);
                acc[f][1] = fma2(rb[q], w[q], acc[f][1]);
                acc[f][1] = fma2(ra[q], x[q], acc[f][1]);
            }
        }
    } else {
        const unsigned wb1 = wbhw + TAPB;         // kd = 1 weights
        #pragma unroll
        for (int f = 0; f < FF; f++) {
            u64 w[4];
            lds128(w[0], w[1], wb1 + f * 64);
            lds128(w[2], w[3], wb1 + f * 64 + 16);
            #pragma unroll
            for (int q = 0; q < 4; q++) {
                acc[f][0] = fma2(ra[q], w[q], acc[f][0]);
                acc[f][1] = fma2(rb[q], w[q], acc[f][1]);
            }
        }
    }
}

// Block: 256 threads = 8 warps. Warp w: wo = blockIdx.x*4 + w/2, parity = w&1.
// Lane: cg = lane&1 owns channels [cg*8, cg*8+8); d16 = lane>>1 owns depth
// slabs s = 2*d16 + j, j in {0,1}. Valid (kh,kw,kd) taps are precomputed from
// the three warp-uniform parity bits (ho&1, wo&1, (bpv+par)&1) — no dead tap
// slots, no per-tap predicate machinery.
__global__ __launch_bounds__(256, 3)
void sparse_conv3d_transpose_kernel(const float* __restrict__ images,
                                    const int*   __restrict__ base_plane,
                                    const float* __restrict__ kernel,
                                    const float* __restrict__ defv,
                                    float*       __restrict__ out)
{
    __shared__ __align__(16) float sw[27 * FF * CC];   // 13824 B
    for (int i = threadIdx.x; i < 27 * FF * CC; i += 256) sw[i] = kernel[i];
    __syncthreads();

    const int b    = blockIdx.z;
    const int ho   = blockIdx.y;
    const int warp = threadIdx.x >> 5;
    const int lane = threadIdx.x & 31;
    const int wo   = (blockIdx.x << 2) + (warp >> 1);
    const int par  = warp & 1;
    const int cg   = lane & 1;
    const int d16  = lane >> 1;

    const u64 dv2 = pack2(*defv);
    const int bpv = __ldg(base_plane + (b * HO + ho) * WO + wo);
    const int m   = bpv + par;

    const unsigned swbase = (unsigned)__cvta_generic_to_shared(sw) + (unsigned)(cg * 32);

    u64 acc[FF][2];
    #pragma unroll
    for (int f = 0; f < FF; f++) { acc[f][0] = 0ull; acc[f][1] = 0ull; }

    // --- precompute valid spatial taps (warp-uniform, <=2 each) ---
    int hi0, hi1 = 0, nh;
    unsigned wbh0, wbh1 = 0;                       // kh * 9 * TAPB
    if (ho & 1) {
        if (ho == HO - 1) { nh = 1; hi0 = (ho - 1) >> 1; wbh0 = 2u * 9 * TAPB; }
        else { nh = 2; hi0 = (ho + 1) >> 1; wbh0 = 0;
               hi1 = (ho - 1) >> 1; wbh1 = 2u * 9 * TAPB; }
    } else { nh = 1; hi0 = ho >> 1; wbh0 = 1u * 9 * TAPB; }

    int wi0, wi1 = 0, nw;
    unsigned wbw0, wbw1 = 0;                       // kw * 3 * TAPB
    if (wo & 1) {
        if (wo == WO - 1) { nw = 1; wi0 = (wo - 1) >> 1; wbw0 = 2u * 3 * TAPB; }
        else { nw = 2; wi0 = (wo + 1) >> 1; wbw0 = 0;
               wi1 = (wo - 1) >> 1; wbw1 = 2u * 3 * TAPB; }
    } else { nw = 1; wi0 = wo >> 1; wbw0 = 1u * 3 * TAPB; }

    auto spatial = [&](auto modd_c) {
        constexpr bool MODD = decltype(modd_c)::value;
        const int off = MODD ? ((m + 1) >> 1) : (m >> 1);
        #pragma unroll 1
        for (int a = 0; a < nh; a++) {
            const int hi       = a ? hi1 : hi0;
            const unsigned wbh = a ? wbh1 : wbh0;
            const int bprow    = (b * HO + (hi << 1)) * WO;
            const float* hrow  = images + (size_t)((b * HI + hi) * WI) * DI * CC;
            #pragma unroll 1
            for (int c = 0; c < nw; c++) {
                const int wi       = c ? wi1 : wi0;
                const unsigned wbw = c ? wbw1 : wbw0;
                const int bpg = __ldg(base_plane + bprow + (wi << 1)) >> 1;
                const float* irow = hrow + (size_t)wi * DI * CC + cg * 8;
                const int r0 = 2 * d16 + off - bpg;
                pixel_taps<MODD>(irow, swbase + wbh + wbw, r0, dv2, acc);
            }
        }
    };

    if (m & 1) spatial(std::integral_constant<bool, true>{});
    else       spatial(std::integral_constant<bool, false>{});

    // Reduce across the cg pair (other 8 channels); keep slab j == cg so the
    // owned output slab index equals `lane` (coalesced stores).
    float r[FF];
    #pragma unroll
    for (int f = 0; f < FF; f++) {
        const u64 a0 = add2(acc[f][0], __shfl_xor_sync(0xffffffffu, acc[f][0], 1));
        const u64 a1 = add2(acc[f][1], __shfl_xor_sync(0xffffffffu, acc[f][1], 1));
        const u64 mine = cg ? a1 : a0;
        r[f] = lo32(mine) + hi32(mine);
    }

    const int dout = 2 * lane + par;
    float4* op = (float4*)(out + (((size_t)((b * HO + ho) * WO + wo) * DO_ + dout) * FF));
    op[0] = make_float4(r[0], r[1], r[2], r[3]);
    op[1] = make_float4(r[4], r[5], r[6], r[7]);
}

extern "C" void kernel_launch(void* const* d_in, const int* in_sizes, int n_in,
                              void* d_out, int out_size)
{
    const float* images     = (const float*)d_in[0];   // [2,64,64,32,16] f32
    const int*   base_plane = (const int*)  d_in[1];   // [2,128,128,1] i32
    const float* kern       = (const float*)d_in[2];   // [3,3,3,8,16] f32
    const float* defv       = (const float*)d_in[3];   // scalar f32 (zero)
    float*       out        = (float*)d_out;           // [2,128,128,64,8] f32

    dim3 grid(WO / 4, HO, B_);
    sparse_conv3d_transpose_kernel<<<grid, 256>>>(images, base_plane, kern, defv, out);
}